// round 5
// baseline (speedup 1.0000x reference)
#include <cuda_runtime.h>

#define BATCHES 4
#define MBOX    128
#define TPB     256
#define GRIDW   32
#define NCELL   (GRIDW * GRIDW)
#define CAP     128   // == MBOX: overflow structurally impossible

// Prebuilt per-batch spatial hash (scratch in device globals — allowed).
__device__ float4        g_boxA[BATCHES][MBOX];        // (cx, cy, cos, sin)
__device__ float4        g_boxB[BATCHES][MBOX];        // (hx, hy, cz, hz)
__device__ int           g_cnt [BATCHES][NCELL];
__device__ unsigned char g_lst [BATCHES][NCELL][CAP];

__global__ __launch_bounds__(TPB)
void pib_build(const float* __restrict__ boxes)
{
    const int b = blockIdx.x;
    const int t = threadIdx.x;

    // Re-zero counts every launch (graph replays this kernel).
    #pragma unroll
    for (int c = t; c < NCELL; c += TPB) g_cnt[b][c] = 0;
    __syncthreads();

    const float inv_cell = (float)GRIDW / 100.0f;   // 0.32
    const float org      = -50.0f;

    if (t < MBOX) {
        const float* bx = boxes + ((size_t)b * MBOX + t) * 7;
        float cx = bx[0], cy = bx[1], cz = bx[2];
        float hx = 0.5f * bx[3], hy = 0.5f * bx[4], hz = 0.5f * bx[5];
        float s, c;
        __sincosf(bx[6], &s, &c);
        g_boxA[b][t] = make_float4(cx, cy, c, s);
        g_boxB[b][t] = make_float4(hx, hy, cz, hz);

        // Conservative AABB of the rotated footprint, inflated well past
        // any fp rounding slack in the in-box test (~1e-5).
        float ac = fabsf(c), as = fabsf(s);
        float ex = hx * ac + hy * as + 1e-3f;
        float ey = hx * as + hy * ac + 1e-3f;

        int xlo = min(max((int)floorf((cx - ex - org) * inv_cell), 0), GRIDW - 1);
        int xhi = min(max((int)floorf((cx + ex - org) * inv_cell), 0), GRIDW - 1);
        int ylo = min(max((int)floorf((cy - ey - org) * inv_cell), 0), GRIDW - 1);
        int yhi = min(max((int)floorf((cy + ey - org) * inv_cell), 0), GRIDW - 1);

        for (int yy = ylo; yy <= yhi; ++yy)
            for (int xx = xlo; xx <= xhi; ++xx) {
                int cell = yy * GRIDW + xx;
                int p = atomicAdd(&g_cnt[b][cell], 1);
                g_lst[b][cell][p] = (unsigned char)t;
            }
    }
}

__global__ __launch_bounds__(TPB)
void pib_query(const float* __restrict__ pts,
               float* __restrict__ out,
               int N)
{
    __shared__ float4 sA[MBOX];
    __shared__ float4 sB[MBOX];

    const int bpb = gridDim.x / BATCHES;     // 256
    const int b   = blockIdx.x / bpb;
    const int blk = blockIdx.x % bpb;
    const int t   = threadIdx.x;

    if (t < MBOX) {            // coalesced 4KB copy of preprocessed boxes
        sA[t] = g_boxA[b][t];
        sB[t] = g_boxB[b][t];
    }
    __syncthreads();

    const float inv_cell = (float)GRIDW / 100.0f;
    const float org      = -50.0f;

    const int i = blk * TPB + t;
    const float* p = pts + ((size_t)b * N + i) * 3;
    float x = p[0], y = p[1], z = p[2];

    int ix = min(max((int)floorf((x - org) * inv_cell), 0), GRIDW - 1);
    int iy = min(max((int)floorf((y - org) * inv_cell), 0), GRIDW - 1);
    int cell = iy * GRIDW + ix;
    int n = g_cnt[b][cell];

    int best = MBOX;    // sentinel > any real index
    // 4 candidate indices per lst load; 4 independent box fetches in flight.
    for (int j = 0; j < n; j += 4) {
        uchar4 m4 = *reinterpret_cast<const uchar4*>(&g_lst[b][cell][j]);
        unsigned char mm[4] = { m4.x, m4.y, m4.z, m4.w };
        #pragma unroll
        for (int k = 0; k < 4; ++k) {
            if (j + k < n) {
                int m = mm[k];
                float4 A  = sA[m];
                float4 Bv = sB[m];
                // Bitwise-identical test math to the validated kernel.
                float dx = x - A.x, dy = y - A.y, dz = z - Bv.z;
                float lx = dx * A.z + dy * A.w;
                float ly = dy * A.z - dx * A.w;
                bool in = (fabsf(lx) <= Bv.x) & (fabsf(ly) <= Bv.y) & (fabsf(dz) <= Bv.w);
                int cand = in ? m : MBOX;
                best = min(best, cand);
            }
        }
    }

    out[(size_t)b * N + i] = (best == MBOX) ? -1.0f : (float)best;
}

extern "C" void kernel_launch(void* const* d_in, const int* in_sizes, int n_in,
                              void* d_out, int out_size)
{
    const float* pts   = (const float*)d_in[0];
    const float* boxes = (const float*)d_in[1];
    float* out = (float*)d_out;

    const int N = out_size / BATCHES;             // 65536
    pib_build<<<BATCHES, TPB>>>(boxes);
    const int grid = BATCHES * (N / TPB);         // 1024 blocks
    pib_query<<<grid, TPB>>>(pts, out, N);
}

// round 6
// speedup vs baseline: 1.3988x; 1.3988x over previous
#include <cuda_runtime.h>

#define BATCHES 4
#define MBOX    128
#define TPB     256
#define GRIDW   32
#define NCELL   (GRIDW * GRIDW)
#define CAP     32    // smem list cap; overflow handled by brute-force fallback

__global__ __launch_bounds__(TPB)
void pib_fused(const float* __restrict__ pts,
               const float* __restrict__ boxes,
               float* __restrict__ out,
               int N)
{
    // Preprocessed boxes:
    //   sA[m] = (cx, cy, cos, sin)
    //   sB[m] = (hx, hy, cz, hz)
    __shared__ float4 sA[MBOX];
    __shared__ float4 sB[MBOX];
    __shared__ int    cnt[NCELL];
    __shared__ unsigned char lst[NCELL][CAP];

    const int bpb = gridDim.x / BATCHES;     // 256
    const int b   = blockIdx.x / bpb;
    const int blk = blockIdx.x % bpb;
    const int t   = threadIdx.x;

    #pragma unroll
    for (int c = t; c < NCELL; c += TPB) cnt[c] = 0;
    __syncthreads();

    const float inv_cell = (float)GRIDW / 100.0f;   // 0.32
    const float org      = -50.0f;

    // ---- build: one thread per box ----
    if (t < MBOX) {
        const float* bx = boxes + ((size_t)b * MBOX + t) * 7;
        float cx = bx[0], cy = bx[1], cz = bx[2];
        float hx = 0.5f * bx[3], hy = 0.5f * bx[4], hz = 0.5f * bx[5];
        float s, c;
        __sincosf(bx[6], &s, &c);
        sA[t] = make_float4(cx, cy, c, s);
        sB[t] = make_float4(hx, hy, cz, hz);

        // Conservative AABB of the rotated footprint, inflated well past
        // any fp rounding slack in the in-box test (~1e-5).
        float ac = fabsf(c), as = fabsf(s);
        float ex = hx * ac + hy * as + 1e-3f;
        float ey = hx * as + hy * ac + 1e-3f;

        int xlo = min(max((int)floorf((cx - ex - org) * inv_cell), 0), GRIDW - 1);
        int xhi = min(max((int)floorf((cx + ex - org) * inv_cell), 0), GRIDW - 1);
        int ylo = min(max((int)floorf((cy - ey - org) * inv_cell), 0), GRIDW - 1);
        int yhi = min(max((int)floorf((cy + ey - org) * inv_cell), 0), GRIDW - 1);

        for (int yy = ylo; yy <= yhi; ++yy)
            for (int xx = xlo; xx <= xhi; ++xx) {
                int cell = yy * GRIDW + xx;
                int p = atomicAdd(&cnt[cell], 1);
                if (p < CAP) lst[cell][p] = (unsigned char)t;
            }
    }
    __syncthreads();

    // ---- query: one thread per point ----
    const int i = blk * TPB + t;
    const float* p = pts + ((size_t)b * N + i) * 3;
    float x = p[0], y = p[1], z = p[2];

    int ix = min(max((int)floorf((x - org) * inv_cell), 0), GRIDW - 1);
    int iy = min(max((int)floorf((y - org) * inv_cell), 0), GRIDW - 1);
    int cell = iy * GRIDW + ix;
    int n = cnt[cell];

    int best = MBOX;    // sentinel > any real index

    if (n <= CAP) {
        // 4 candidate indices per LDS.32; 4 independent box tests in flight.
        for (int j = 0; j < n; j += 4) {
            uchar4 m4 = *reinterpret_cast<const uchar4*>(&lst[cell][j]);
            unsigned char mm[4] = { m4.x, m4.y, m4.z, m4.w };
            #pragma unroll
            for (int k = 0; k < 4; ++k) {
                if (j + k < n) {
                    int m = mm[k];
                    float4 A  = sA[m];
                    float4 Bv = sB[m];
                    // Bitwise-identical test math to the validated kernel.
                    float dx = x - A.x, dy = y - A.y, dz = z - Bv.z;
                    float lx = dx * A.z + dy * A.w;
                    float ly = dy * A.z - dx * A.w;
                    bool in = (fabsf(lx) <= Bv.x) & (fabsf(ly) <= Bv.y) & (fabsf(dz) <= Bv.w);
                    int cand = in ? m : MBOX;
                    best = min(best, cand);
                }
            }
        }
    } else {
        // Structural overflow fallback: test every box (never skips a hit).
        for (int m = 0; m < MBOX; ++m) {
            float4 A  = sA[m];
            float4 Bv = sB[m];
            float dx = x - A.x, dy = y - A.y, dz = z - Bv.z;
            float lx = dx * A.z + dy * A.w;
            float ly = dy * A.z - dx * A.w;
            bool in = (fabsf(lx) <= Bv.x) & (fabsf(ly) <= Bv.y) & (fabsf(dz) <= Bv.w);
            int cand = in ? m : MBOX;
            best = min(best, cand);
        }
    }

    out[(size_t)b * N + i] = (best == MBOX) ? -1.0f : (float)best;
}

extern "C" void kernel_launch(void* const* d_in, const int* in_sizes, int n_in,
                              void* d_out, int out_size)
{
    const float* pts   = (const float*)d_in[0];
    const float* boxes = (const float*)d_in[1];
    float* out = (float*)d_out;

    const int N = out_size / BATCHES;             // 65536
    const int grid = BATCHES * (N / TPB);         // 1024 blocks
    pib_fused<<<grid, TPB>>>(pts, boxes, out, N);
}

// round 7
// speedup vs baseline: 1.6151x; 1.1547x over previous
#include <cuda_runtime.h>

#define BATCHES 4
#define MBOX    128
#define TPB     256
#define PPT     2
#define GRIDW   32
#define NCELL   (GRIDW * GRIDW)
#define CAP     32    // smem list cap; overflow handled by brute-force fallback

__global__ __launch_bounds__(TPB)
void pib_fused(const float* __restrict__ pts,
               const float* __restrict__ boxes,
               float* __restrict__ out,
               int N)
{
    // Preprocessed boxes:
    //   sA[m] = (cx, cy, cos, sin)
    //   sB[m] = (hx, hy, cz, hz)
    __shared__ float4 sA[MBOX];
    __shared__ float4 sB[MBOX];
    __shared__ int    cnt[NCELL];
    __shared__ unsigned char lst[NCELL][CAP];

    const int bpb = gridDim.x / BATCHES;     // 128
    const int b   = blockIdx.x / bpb;
    const int blk = blockIdx.x % bpb;
    const int t   = threadIdx.x;

    // Zero counters: one STS.128 per thread.
    {
        int4 z = make_int4(0, 0, 0, 0);
        #pragma unroll
        for (int c4 = t; c4 < NCELL / 4; c4 += TPB)
            reinterpret_cast<int4*>(cnt)[c4] = z;
    }
    __syncthreads();

    const float inv_cell = (float)GRIDW / 100.0f;   // 0.32
    const float org      = -50.0f;

    // ---- build: one thread per box ----
    if (t < MBOX) {
        const float* bx = boxes + ((size_t)b * MBOX + t) * 7;
        float cx = bx[0], cy = bx[1], cz = bx[2];
        float hx = 0.5f * bx[3], hy = 0.5f * bx[4], hz = 0.5f * bx[5];
        float s, c;
        __sincosf(bx[6], &s, &c);
        sA[t] = make_float4(cx, cy, c, s);
        sB[t] = make_float4(hx, hy, cz, hz);

        // Conservative AABB of the rotated footprint, inflated well past
        // any fp rounding slack in the in-box test (~1e-5).
        float ac = fabsf(c), as = fabsf(s);
        float ex = hx * ac + hy * as + 1e-3f;
        float ey = hx * as + hy * ac + 1e-3f;

        int xlo = min(max((int)floorf((cx - ex - org) * inv_cell), 0), GRIDW - 1);
        int xhi = min(max((int)floorf((cx + ex - org) * inv_cell), 0), GRIDW - 1);
        int ylo = min(max((int)floorf((cy - ey - org) * inv_cell), 0), GRIDW - 1);
        int yhi = min(max((int)floorf((cy + ey - org) * inv_cell), 0), GRIDW - 1);

        for (int yy = ylo; yy <= yhi; ++yy)
            for (int xx = xlo; xx <= xhi; ++xx) {
                int cell = yy * GRIDW + xx;
                int p = atomicAdd(&cnt[cell], 1);
                if (p < CAP) lst[cell][p] = (unsigned char)t;
            }
    }
    __syncthreads();

    // ---- query: two points per thread, interleaved for ILP ----
    const int i0 = (blk * TPB + t) * PPT;
    const float2* p2 = reinterpret_cast<const float2*>(pts + ((size_t)b * N + i0) * 3);
    float2 qa = p2[0], qb = p2[1], qc = p2[2];
    float x0 = qa.x, y0 = qa.y, z0 = qb.x;
    float x1 = qb.y, y1 = qc.x, z1 = qc.y;

    int ix0 = min(max((int)floorf((x0 - org) * inv_cell), 0), GRIDW - 1);
    int iy0 = min(max((int)floorf((y0 - org) * inv_cell), 0), GRIDW - 1);
    int ix1 = min(max((int)floorf((x1 - org) * inv_cell), 0), GRIDW - 1);
    int iy1 = min(max((int)floorf((y1 - org) * inv_cell), 0), GRIDW - 1);
    int cell0 = iy0 * GRIDW + ix0;
    int cell1 = iy1 * GRIDW + ix1;
    int n0 = cnt[cell0];
    int n1 = cnt[cell1];

    // List-scan trip counts (0 if overflowed; handled by fallback below).
    int l0 = (n0 <= CAP) ? n0 : 0;
    int l1 = (n1 <= CAP) ? n1 : 0;
    int nmax = max(l0, l1);

    int best0 = MBOX, best1 = MBOX;

    for (int j = 0; j < nmax; j += 4) {
        // Unconditional in-bounds smem reads (j < CAP); lanes masked below.
        uchar4 m40 = *reinterpret_cast<const uchar4*>(&lst[cell0][j]);
        uchar4 m41 = *reinterpret_cast<const uchar4*>(&lst[cell1][j]);
        unsigned char a[4] = { m40.x, m40.y, m40.z, m40.w };
        unsigned char d[4] = { m41.x, m41.y, m41.z, m41.w };
        #pragma unroll
        for (int k = 0; k < 4; ++k) {
            if (j + k < l0) {
                int m = a[k];
                float4 A  = sA[m];
                float4 Bv = sB[m];
                float dx = x0 - A.x, dy = y0 - A.y, dz = z0 - Bv.z;
                float lx = dx * A.z + dy * A.w;
                float ly = dy * A.z - dx * A.w;
                bool in = (fabsf(lx) <= Bv.x) & (fabsf(ly) <= Bv.y) & (fabsf(dz) <= Bv.w);
                best0 = min(best0, in ? m : MBOX);
            }
            if (j + k < l1) {
                int m = d[k];
                float4 A  = sA[m];
                float4 Bv = sB[m];
                float dx = x1 - A.x, dy = y1 - A.y, dz = z1 - Bv.z;
                float lx = dx * A.z + dy * A.w;
                float ly = dy * A.z - dx * A.w;
                bool in = (fabsf(lx) <= Bv.x) & (fabsf(ly) <= Bv.y) & (fabsf(dz) <= Bv.w);
                best1 = min(best1, in ? m : MBOX);
            }
        }
    }

    // Structural overflow fallback: test every box (never skips a hit).
    if ((n0 > CAP) | (n1 > CAP)) {
        for (int m = 0; m < MBOX; ++m) {
            float4 A  = sA[m];
            float4 Bv = sB[m];
            if (n0 > CAP) {
                float dx = x0 - A.x, dy = y0 - A.y, dz = z0 - Bv.z;
                float lx = dx * A.z + dy * A.w;
                float ly = dy * A.z - dx * A.w;
                bool in = (fabsf(lx) <= Bv.x) & (fabsf(ly) <= Bv.y) & (fabsf(dz) <= Bv.w);
                best0 = min(best0, in ? m : MBOX);
            }
            if (n1 > CAP) {
                float dx = x1 - A.x, dy = y1 - A.y, dz = z1 - Bv.z;
                float lx = dx * A.z + dy * A.w;
                float ly = dy * A.z - dx * A.w;
                bool in = (fabsf(lx) <= Bv.x) & (fabsf(ly) <= Bv.y) & (fabsf(dz) <= Bv.w);
                best1 = min(best1, in ? m : MBOX);
            }
        }
    }

    float2 o = make_float2((best0 == MBOX) ? -1.0f : (float)best0,
                           (best1 == MBOX) ? -1.0f : (float)best1);
    *reinterpret_cast<float2*>(out + (size_t)b * N + i0) = o;
}

extern "C" void kernel_launch(void* const* d_in, const int* in_sizes, int n_in,
                              void* d_out, int out_size)
{
    const float* pts   = (const float*)d_in[0];
    const float* boxes = (const float*)d_in[1];
    float* out = (float*)d_out;

    const int N = out_size / BATCHES;                 // 65536
    const int grid = BATCHES * (N / (TPB * PPT));     // 4 * 128 = 512 blocks
    pib_fused<<<grid, TPB>>>(pts, boxes, out, N);
}

// round 8
// speedup vs baseline: 1.6880x; 1.0451x over previous
#include <cuda_runtime.h>

#define BATCHES 4
#define MBOX    128
#define TPB     256
#define PPT     2
#define GRIDW   32
#define NCELL   (GRIDW * GRIDW)
#define CAP     32    // smem list cap; overflow handled by brute-force fallback
#define BOXF    7     // floats per box

__global__ __launch_bounds__(TPB)
void pib_fused(const float* __restrict__ pts,
               const float* __restrict__ boxes,
               float* __restrict__ out,
               int N)
{
    // Preprocessed boxes:
    //   sA[m] = (cx, cy, cos, sin)
    //   sB[m] = (hx, hy, cz, hz)
    __shared__ float4 sA[MBOX];
    __shared__ float4 sB[MBOX];
    __shared__ int    cnt[NCELL];
    __shared__ unsigned char lst[NCELL][CAP];
    __shared__ float  sRaw[MBOX * BOXF];          // coalesced staging (3.5 KB)

    const int bpb = gridDim.x / BATCHES;     // 128
    const int b   = blockIdx.x / bpb;
    const int blk = blockIdx.x % bpb;
    const int t   = threadIdx.x;

    // Zero counters (one STS.128 per thread) + coalesced box staging.
    {
        int4 z = make_int4(0, 0, 0, 0);
        reinterpret_cast<int4*>(cnt)[t] = z;      // NCELL/4 == TPB
        const float* src = boxes + (size_t)b * MBOX * BOXF;
        #pragma unroll
        for (int i = t; i < MBOX * BOXF; i += TPB)
            sRaw[i] = src[i];
    }
    __syncthreads();

    const float inv_cell = (float)GRIDW / 100.0f;   // 0.32
    const float org      = -50.0f;

    // ---- build: one thread per box, reading staged smem ----
    if (t < MBOX) {
        const float* bx = &sRaw[t * BOXF];
        float cx = bx[0], cy = bx[1], cz = bx[2];
        float hx = 0.5f * bx[3], hy = 0.5f * bx[4], hz = 0.5f * bx[5];
        float s, c;
        __sincosf(bx[6], &s, &c);
        sA[t] = make_float4(cx, cy, c, s);
        sB[t] = make_float4(hx, hy, cz, hz);

        // Conservative AABB of the rotated footprint, inflated well past
        // any fp rounding slack in the in-box test (~1e-5).
        float ac = fabsf(c), as = fabsf(s);
        float ex = hx * ac + hy * as + 1e-3f;
        float ey = hx * as + hy * ac + 1e-3f;

        int xlo = min(max((int)floorf((cx - ex - org) * inv_cell), 0), GRIDW - 1);
        int xhi = min(max((int)floorf((cx + ex - org) * inv_cell), 0), GRIDW - 1);
        int ylo = min(max((int)floorf((cy - ey - org) * inv_cell), 0), GRIDW - 1);
        int yhi = min(max((int)floorf((cy + ey - org) * inv_cell), 0), GRIDW - 1);

        for (int yy = ylo; yy <= yhi; ++yy)
            for (int xx = xlo; xx <= xhi; ++xx) {
                int cell = yy * GRIDW + xx;
                int p = atomicAdd(&cnt[cell], 1);
                if (p < CAP) lst[cell][p] = (unsigned char)t;
            }
    }
    __syncthreads();

    // ---- query: two points per thread, interleaved, guard-free ----
    // Safety: evaluating the exact test against ANY box index is correct-
    // neutral (a true hit implies the box is in the point's cell list, so
    // min() is unchanged; a false hit contributes nothing). Hence entries
    // past a cell's count may be garbage; we only clamp to &127 for bounds.
    const int i0 = (blk * TPB + t) * PPT;
    const float2* p2 = reinterpret_cast<const float2*>(pts + ((size_t)b * N + i0) * 3);
    float2 qa = p2[0], qb = p2[1], qc = p2[2];
    float x0 = qa.x, y0 = qa.y, z0 = qb.x;
    float x1 = qb.y, y1 = qc.x, z1 = qc.y;

    int ix0 = min(max((int)floorf((x0 - org) * inv_cell), 0), GRIDW - 1);
    int iy0 = min(max((int)floorf((y0 - org) * inv_cell), 0), GRIDW - 1);
    int ix1 = min(max((int)floorf((x1 - org) * inv_cell), 0), GRIDW - 1);
    int iy1 = min(max((int)floorf((y1 - org) * inv_cell), 0), GRIDW - 1);
    int cell0 = iy0 * GRIDW + ix0;
    int cell1 = iy1 * GRIDW + ix1;
    int n0 = cnt[cell0];
    int n1 = cnt[cell1];

    int l0 = (n0 <= CAP) ? n0 : 0;
    int l1 = (n1 <= CAP) ? n1 : 0;
    int nmax = (max(l0, l1) + 3) & ~3;            // <= CAP, multiple of 4

    int best0 = MBOX, best1 = MBOX;

    for (int j = 0; j < nmax; j += 4) {
        unsigned int u0 = *reinterpret_cast<const unsigned int*>(&lst[cell0][j]);
        unsigned int u1 = *reinterpret_cast<const unsigned int*>(&lst[cell1][j]);
        #pragma unroll
        for (int k = 0; k < 4; ++k) {
            {
                int m = (u0 >> (8 * k)) & 127;
                float4 A  = sA[m];
                float4 Bv = sB[m];
                float dx = x0 - A.x, dy = y0 - A.y, dz = z0 - Bv.z;
                float lx = dx * A.z + dy * A.w;
                float ly = dy * A.z - dx * A.w;
                bool in = (fabsf(lx) <= Bv.x) & (fabsf(ly) <= Bv.y) & (fabsf(dz) <= Bv.w);
                best0 = min(best0, in ? m : MBOX);
            }
            {
                int m = (u1 >> (8 * k)) & 127;
                float4 A  = sA[m];
                float4 Bv = sB[m];
                float dx = x1 - A.x, dy = y1 - A.y, dz = z1 - Bv.z;
                float lx = dx * A.z + dy * A.w;
                float ly = dy * A.z - dx * A.w;
                bool in = (fabsf(lx) <= Bv.x) & (fabsf(ly) <= Bv.y) & (fabsf(dz) <= Bv.w);
                best1 = min(best1, in ? m : MBOX);
            }
        }
    }

    // Structural overflow fallback: test every box (never skips a hit).
    if ((n0 > CAP) | (n1 > CAP)) {
        for (int m = 0; m < MBOX; ++m) {
            float4 A  = sA[m];
            float4 Bv = sB[m];
            if (n0 > CAP) {
                float dx = x0 - A.x, dy = y0 - A.y, dz = z0 - Bv.z;
                float lx = dx * A.z + dy * A.w;
                float ly = dy * A.z - dx * A.w;
                bool in = (fabsf(lx) <= Bv.x) & (fabsf(ly) <= Bv.y) & (fabsf(dz) <= Bv.w);
                best0 = min(best0, in ? m : MBOX);
            }
            if (n1 > CAP) {
                float dx = x1 - A.x, dy = y1 - A.y, dz = z1 - Bv.z;
                float lx = dx * A.z + dy * A.w;
                float ly = dy * A.z - dx * A.w;
                bool in = (fabsf(lx) <= Bv.x) & (fabsf(ly) <= Bv.y) & (fabsf(dz) <= Bv.w);
                best1 = min(best1, in ? m : MBOX);
            }
        }
    }

    float2 o = make_float2((best0 == MBOX) ? -1.0f : (float)best0,
                           (best1 == MBOX) ? -1.0f : (float)best1);
    *reinterpret_cast<float2*>(out + (size_t)b * N + i0) = o;
}

extern "C" void kernel_launch(void* const* d_in, const int* in_sizes, int n_in,
                              void* d_out, int out_size)
{
    const float* pts   = (const float*)d_in[0];
    const float* boxes = (const float*)d_in[1];
    float* out = (float*)d_out;

    const int N = out_size / BATCHES;                 // 65536
    const int grid = BATCHES * (N / (TPB * PPT));     // 4 * 128 = 512 blocks
    pib_fused<<<grid, TPB>>>(pts, boxes, out, N);
}